// round 1
// baseline (speedup 1.0000x reference)
#include <cuda_runtime.h>
#include <math.h>

#define HIDDEN 3072
#define NH     32
#define HD     96
#define OPSZ   9216   // 32*96 + 2*32*96
#define BB     2
#define LL     2048
#define MTOK   4096   // BB*LL

// ---------------- scratch (static device globals; no allocation) ----------------
__device__ float g_qkv[(size_t)MTOK * OPSZ];    // [token, 9216] : q | k | v
__device__ float g_attn[(size_t)MTOK * HIDDEN]; // [token, 3072]
__device__ float g_cos[LL * 48];
__device__ float g_sin[LL * 48];

// ---------------- RoPE table (double precision phases) ----------------
__global__ void rope_table_kernel() {
    int idx = blockIdx.x * blockDim.x + threadIdx.x;
    if (idx >= LL * 48) return;
    int i = idx % 48;
    int l = idx / 48;
    // inv_freq = 10000^{-i/48}; scaling = sqrt(1 + ln(32)/ln(4096)) = sqrt(17/12)
    double invf = exp(-(double)i / 48.0 * log(10000.0));
    double ang  = (double)l * invf;
    double S    = sqrt(17.0 / 12.0);
    double s, c;
    sincos(ang, &s, &c);
    g_cos[idx] = (float)(c * S);
    g_sin[idx] = (float)(s * S);
}

// ---------------- RoPE apply (in-place on q,k slices of g_qkv) ----------------
__global__ void rope_apply_kernel() {
    int idx = blockIdx.x * blockDim.x + threadIdx.x;
    const int total = MTOK * NH * 48;
    if (idx >= total) return;
    int i = idx % 48;
    int h = (idx / 48) % NH;
    int t = idx / (48 * NH);       // token 0..4095
    int l = t & (LL - 1);
    float c = g_cos[l * 48 + i];
    float s = g_sin[l * 48 + i];
    float* qb = g_qkv + (size_t)t * OPSZ + h * HD;
    float q0 = qb[i], q1 = qb[i + 48];
    qb[i]      = q0 * c - q1 * s;
    qb[i + 48] = q1 * c + q0 * s;
    float* kb = qb + 3072;
    float k0 = kb[i], k1 = kb[i + 48];
    kb[i]      = k0 * c - k1 * s;
    kb[i + 48] = k1 * c + k0 * s;
}

// ---------------- tiled SGEMM: C[M,N] = A[M,K] * B[N,K]^T ----------------
// BM=BN=128, BK=8, 256 threads, 8x8 per thread (split 4+4 at +64 offsets).
__global__ __launch_bounds__(256) void gemm_nt_kernel(
    const float* __restrict__ A, const float* __restrict__ Bm,
    float* __restrict__ C, int M, int N, int K)
{
    __shared__ float As[8][128];
    __shared__ float Bs[8][128];
    const int tid = threadIdx.x;
    const int bm = blockIdx.y * 128;
    const int bn = blockIdx.x * 128;
    const int ry = tid >> 4;          // 0..15
    const int rx = tid & 15;          // 0..15
    const int lrow = tid >> 1;        // 0..127
    const int lcol = (tid & 1) << 2;  // 0 or 4

    const float* Ap = A  + (size_t)(bm + lrow) * K + lcol;
    const float* Bp = Bm + (size_t)(bn + lrow) * K + lcol;

    float acc[8][8];
#pragma unroll
    for (int i = 0; i < 8; i++)
#pragma unroll
        for (int j = 0; j < 8; j++) acc[i][j] = 0.0f;

    for (int kb = 0; kb < K; kb += 8) {
        float4 a = *(const float4*)(Ap + kb);
        float4 b = *(const float4*)(Bp + kb);
        As[lcol + 0][lrow] = a.x; As[lcol + 1][lrow] = a.y;
        As[lcol + 2][lrow] = a.z; As[lcol + 3][lrow] = a.w;
        Bs[lcol + 0][lrow] = b.x; Bs[lcol + 1][lrow] = b.y;
        Bs[lcol + 2][lrow] = b.z; Bs[lcol + 3][lrow] = b.w;
        __syncthreads();
#pragma unroll
        for (int kk = 0; kk < 8; kk++) {
            float4 a0 = *(const float4*)&As[kk][ry * 4];
            float4 a1 = *(const float4*)&As[kk][ry * 4 + 64];
            float4 b0 = *(const float4*)&Bs[kk][rx * 4];
            float4 b1 = *(const float4*)&Bs[kk][rx * 4 + 64];
            float av[8] = {a0.x, a0.y, a0.z, a0.w, a1.x, a1.y, a1.z, a1.w};
            float bv[8] = {b0.x, b0.y, b0.z, b0.w, b1.x, b1.y, b1.z, b1.w};
#pragma unroll
            for (int i = 0; i < 8; i++)
#pragma unroll
                for (int j = 0; j < 8; j++)
                    acc[i][j] = fmaf(av[i], bv[j], acc[i][j]);
        }
        __syncthreads();
    }

#pragma unroll
    for (int ih = 0; ih < 2; ih++)
#pragma unroll
        for (int i = 0; i < 4; i++) {
            int row = bm + ih * 64 + ry * 4 + i;
            float* Cp = C + (size_t)row * N + bn;
            int ai = ih * 4 + i;
            *(float4*)(Cp + rx * 4) =
                make_float4(acc[ai][0], acc[ai][1], acc[ai][2], acc[ai][3]);
            *(float4*)(Cp + 64 + rx * 4) =
                make_float4(acc[ai][4], acc[ai][5], acc[ai][6], acc[ai][7]);
        }
}

// ---------------- fp32 flash attention ----------------
// grid: (32 q-tiles, 64 b*h). block: 256 threads (16x16).
// Thread (ty,tx): S tile rows ty*4..+3, cols tx*4..+3 ; O tile rows ty*4..+3, cols tx*6..+5.
#define BQ 64
#define BKV 64
#define QP 97   // pitch for Q/K rows (96 data + 1 pad -> bank stride 1)
#define PP 65   // pitch for P rows
#define FLASH_SMEM_FLOATS (BQ*QP + BKV*QP + BKV*HD + BQ*PP)

__global__ __launch_bounds__(256) void flash_kernel(
    const float* __restrict__ qkv, float* __restrict__ out)
{
    extern __shared__ float sm[];
    float* Qs = sm;                   // BQ * QP
    float* Ks = Qs + BQ * QP;         // BKV * QP
    float* Vs = Ks + BKV * QP;        // BKV * HD
    float* Ps = Vs + BKV * HD;        // BQ * PP

    const int qt  = blockIdx.x;       // 0..31
    const int bh  = blockIdx.y;       // 0..63
    const int b   = bh >> 5;
    const int h   = bh & 31;
    const int tid = threadIdx.x;
    const int ty  = tid >> 4;
    const int tx  = tid & 15;

    const float scale = 0.10206207261596577f;  // 96^-0.5

    const float* qbase = qkv + (size_t)b * LL * OPSZ + h * HD;
    const float* kbase = qbase + 3072;
    const float* vbase = qbase + 6144;

    // load Q tile (scaled)
    for (int idx = tid; idx < BQ * HD; idx += 256) {
        int r = idx / HD, d = idx % HD;
        Qs[r * QP + d] = qbase[(size_t)(qt * BQ + r) * OPSZ + d] * scale;
    }

    float m[4], l[4], acc[4][6];
#pragma unroll
    for (int i = 0; i < 4; i++) {
        m[i] = -INFINITY; l[i] = 0.0f;
#pragma unroll
        for (int j = 0; j < 6; j++) acc[i][j] = 0.0f;
    }

    __syncthreads();

    for (int kb = 0; kb <= qt; kb++) {
        // barrier: previous iteration's PV reads of Ks/Vs/Ps must finish
        __syncthreads();
        for (int idx = tid; idx < BKV * HD; idx += 256) {
            int r = idx / HD, d = idx % HD;
            Ks[r * QP + d] = kbase[(size_t)(kb * BKV + r) * OPSZ + d];
            Vs[r * HD + d] = vbase[(size_t)(kb * BKV + r) * OPSZ + d];
        }
        __syncthreads();

        // S = Q K^T  (4x4 per thread)
        float s[4][4];
#pragma unroll
        for (int i = 0; i < 4; i++)
#pragma unroll
            for (int j = 0; j < 4; j++) s[i][j] = 0.0f;

#pragma unroll 4
        for (int kk = 0; kk < HD; kk++) {
            float qv[4], kv[4];
#pragma unroll
            for (int i = 0; i < 4; i++) qv[i] = Qs[(ty * 4 + i) * QP + kk];
#pragma unroll
            for (int j = 0; j < 4; j++) kv[j] = Ks[(tx * 4 + j) * QP + kk];
#pragma unroll
            for (int i = 0; i < 4; i++)
#pragma unroll
                for (int j = 0; j < 4; j++)
                    s[i][j] = fmaf(qv[i], kv[j], s[i][j]);
        }

        // causal mask only on diagonal block
        if (kb == qt) {
#pragma unroll
            for (int i = 0; i < 4; i++) {
                int r = ty * 4 + i;
#pragma unroll
                for (int j = 0; j < 4; j++) {
                    int c = tx * 4 + j;
                    if (c > r) s[i][j] = -INFINITY;
                }
            }
        }

        // online softmax per row (reduce across 16 tx lanes)
#pragma unroll
        for (int i = 0; i < 4; i++) {
            float mx = fmaxf(fmaxf(s[i][0], s[i][1]), fmaxf(s[i][2], s[i][3]));
#pragma unroll
            for (int off = 8; off >= 1; off >>= 1)
                mx = fmaxf(mx, __shfl_xor_sync(0xffffffffu, mx, off));
            float mnew  = fmaxf(m[i], mx);
            float alpha = __expf(m[i] - mnew);
            float psum = 0.0f;
            int r = ty * 4 + i;
#pragma unroll
            for (int j = 0; j < 4; j++) {
                float p = __expf(s[i][j] - mnew);
                Ps[r * PP + tx * 4 + j] = p;
                psum += p;
            }
#pragma unroll
            for (int off = 8; off >= 1; off >>= 1)
                psum += __shfl_xor_sync(0xffffffffu, psum, off);
            l[i] = l[i] * alpha + psum;
            m[i] = mnew;
#pragma unroll
            for (int j = 0; j < 6; j++) acc[i][j] *= alpha;
        }
        __syncthreads();

        // O += P V   (4 rows x 6 cols per thread)
#pragma unroll 4
        for (int kk = 0; kk < BKV; kk++) {
            float vv[6];
#pragma unroll
            for (int j = 0; j < 6; j++) vv[j] = Vs[kk * HD + tx * 6 + j];
#pragma unroll
            for (int i = 0; i < 4; i++) {
                float p = Ps[(ty * 4 + i) * PP + kk];
#pragma unroll
                for (int j = 0; j < 6; j++)
                    acc[i][j] = fmaf(p, vv[j], acc[i][j]);
            }
        }
    }

    // write [b, l, h*96 + d]
#pragma unroll
    for (int i = 0; i < 4; i++) {
        int lrow = qt * BQ + ty * 4 + i;
        float inv = 1.0f / l[i];
        float* op = out + (size_t)(b * LL + lrow) * HIDDEN + h * HD + tx * 6;
#pragma unroll
        for (int j = 0; j < 6; j++) op[j] = acc[i][j] * inv;
    }
}

// ---------------- launch ----------------
extern "C" void kernel_launch(void* const* d_in, const int* in_sizes, int n_in,
                              void* d_out, int out_size)
{
    const float* x    = (const float*)d_in[0];
    const float* Wqkv = (const float*)d_in[1];
    const float* Wo   = (const float*)d_in[2];
    float* out = (float*)d_out;

    float* qkv;  cudaGetSymbolAddress((void**)&qkv,  g_qkv);
    float* attn; cudaGetSymbolAddress((void**)&attn, g_attn);

    // opt-in to >48KB dynamic smem for flash kernel (idempotent, not a stream op)
    static const int flash_smem = FLASH_SMEM_FLOATS * (int)sizeof(float);
    cudaFuncSetAttribute(flash_kernel,
                         cudaFuncAttributeMaxDynamicSharedMemorySize, flash_smem);

    // 1) QKV = x @ Wqkv^T : [4096, 9216]
    {
        dim3 grid(OPSZ / 128, MTOK / 128);
        gemm_nt_kernel<<<grid, 256>>>(x, Wqkv, qkv, MTOK, OPSZ, HIDDEN);
    }
    // 2) RoPE
    {
        int n1 = LL * 48;
        rope_table_kernel<<<(n1 + 255) / 256, 256>>>();
        int n2 = MTOK * NH * 48;
        rope_apply_kernel<<<(n2 + 255) / 256, 256>>>();
    }
    // 3) flash attention -> attn [4096, 3072]
    {
        dim3 grid(LL / BQ, BB * NH);
        flash_kernel<<<grid, 256, flash_smem>>>(qkv, attn);
    }
    // 4) out = attn @ Wo^T : [4096, 3072]
    {
        dim3 grid(HIDDEN / 128, MTOK / 128);
        gemm_nt_kernel<<<grid, 256>>>(attn, Wo, out, MTOK, HIDDEN, HIDDEN);
    }
}

// round 2
// speedup vs baseline: 1.0010x; 1.0010x over previous
#include <cuda_runtime.h>
#include <math.h>

#define HIDDEN 3072
#define NH     32
#define HD     96
#define OPSZ   9216   // 32*96 + 2*32*96
#define BB     2
#define LL     2048
#define MTOK   4096   // BB*LL

// ---------------- scratch (static device globals; no allocation) ----------------
__device__ float g_qkv[(size_t)MTOK * OPSZ];    // [token, 9216] : q | k | v
__device__ float g_attn[(size_t)MTOK * HIDDEN]; // [token, 3072]
__device__ float g_cos[LL * 48];
__device__ float g_sin[LL * 48];

// ---------------- RoPE table (double precision phases) ----------------
__global__ void rope_table_kernel() {
    int idx = blockIdx.x * blockDim.x + threadIdx.x;
    if (idx >= LL * 48) return;
    int i = idx % 48;
    int l = idx / 48;
    // inv_freq = 10000^{-i/48}; scaling = sqrt(1 + ln(32)/ln(4096)) = sqrt(17/12)
    double invf = exp(-(double)i / 48.0 * log(10000.0));
    double ang  = (double)l * invf;
    double S    = sqrt(17.0 / 12.0);
    double s, c;
    sincos(ang, &s, &c);
    g_cos[idx] = (float)(c * S);
    g_sin[idx] = (float)(s * S);
}

// ---------------- RoPE apply (in-place on q,k slices of g_qkv) ----------------
__global__ void rope_apply_kernel() {
    int idx = blockIdx.x * blockDim.x + threadIdx.x;
    const int total = MTOK * NH * 48;
    if (idx >= total) return;
    int i = idx % 48;
    int h = (idx / 48) % NH;
    int t = idx / (48 * NH);       // token 0..4095
    int l = t & (LL - 1);
    float c = g_cos[l * 48 + i];
    float s = g_sin[l * 48 + i];
    float* qb = g_qkv + (size_t)t * OPSZ + h * HD;
    float q0 = qb[i], q1 = qb[i + 48];
    qb[i]      = q0 * c - q1 * s;
    qb[i + 48] = q1 * c + q0 * s;
    float* kb = qb + 3072;
    float k0 = kb[i], k1 = kb[i + 48];
    kb[i]      = k0 * c - k1 * s;
    kb[i + 48] = k1 * c + k0 * s;
}

// ---------------- tiled SGEMM: C[M,N] = A[M,K] * B[N,K]^T ----------------
// BM=BN=128, BK=8, 256 threads, 8x8 per thread (split 4+4 at +64 offsets).
__global__ __launch_bounds__(256) void gemm_nt_kernel(
    const float* __restrict__ A, const float* __restrict__ Bm,
    float* __restrict__ C, int M, int N, int K)
{
    __shared__ float As[8][128];
    __shared__ float Bs[8][128];
    const int tid = threadIdx.x;
    const int bm = blockIdx.y * 128;
    const int bn = blockIdx.x * 128;
    const int ry = tid >> 4;          // 0..15
    const int rx = tid & 15;          // 0..15
    const int lrow = tid >> 1;        // 0..127
    const int lcol = (tid & 1) << 2;  // 0 or 4

    const float* Ap = A  + (size_t)(bm + lrow) * K + lcol;
    const float* Bp = Bm + (size_t)(bn + lrow) * K + lcol;

    float acc[8][8];
#pragma unroll
    for (int i = 0; i < 8; i++)
#pragma unroll
        for (int j = 0; j < 8; j++) acc[i][j] = 0.0f;

    for (int kb = 0; kb < K; kb += 8) {
        float4 a = *(const float4*)(Ap + kb);
        float4 b = *(const float4*)(Bp + kb);
        As[lcol + 0][lrow] = a.x; As[lcol + 1][lrow] = a.y;
        As[lcol + 2][lrow] = a.z; As[lcol + 3][lrow] = a.w;
        Bs[lcol + 0][lrow] = b.x; Bs[lcol + 1][lrow] = b.y;
        Bs[lcol + 2][lrow] = b.z; Bs[lcol + 3][lrow] = b.w;
        __syncthreads();
#pragma unroll
        for (int kk = 0; kk < 8; kk++) {
            float4 a0 = *(const float4*)&As[kk][ry * 4];
            float4 a1 = *(const float4*)&As[kk][ry * 4 + 64];
            float4 b0 = *(const float4*)&Bs[kk][rx * 4];
            float4 b1 = *(const float4*)&Bs[kk][rx * 4 + 64];
            float av[8] = {a0.x, a0.y, a0.z, a0.w, a1.x, a1.y, a1.z, a1.w};
            float bv[8] = {b0.x, b0.y, b0.z, b0.w, b1.x, b1.y, b1.z, b1.w};
#pragma unroll
            for (int i = 0; i < 8; i++)
#pragma unroll
                for (int j = 0; j < 8; j++)
                    acc[i][j] = fmaf(av[i], bv[j], acc[i][j]);
        }
        __syncthreads();
    }

#pragma unroll
    for (int ih = 0; ih < 2; ih++)
#pragma unroll
        for (int i = 0; i < 4; i++) {
            int row = bm + ih * 64 + ry * 4 + i;
            float* Cp = C + (size_t)row * N + bn;
            int ai = ih * 4 + i;
            *(float4*)(Cp + rx * 4) =
                make_float4(acc[ai][0], acc[ai][1], acc[ai][2], acc[ai][3]);
            *(float4*)(Cp + 64 + rx * 4) =
                make_float4(acc[ai][4], acc[ai][5], acc[ai][6], acc[ai][7]);
        }
}

// ---------------- fp32 flash attention ----------------
// grid: (32 q-tiles, 64 b*h). block: 256 threads (16x16).
// Thread (ty,tx): S tile rows ty*4..+3, cols tx*4..+3 ; O tile rows ty*4..+3, cols tx*6..+5.
#define BQ 64
#define BKV 64
#define QP 97   // pitch for Q/K rows (96 data + 1 pad -> bank stride 1)
#define PP 65   // pitch for P rows
#define FLASH_SMEM_FLOATS (BQ*QP + BKV*QP + BKV*HD + BQ*PP)

__global__ __launch_bounds__(256) void flash_kernel(
    const float* __restrict__ qkv, float* __restrict__ out)
{
    extern __shared__ float sm[];
    float* Qs = sm;                   // BQ * QP
    float* Ks = Qs + BQ * QP;         // BKV * QP
    float* Vs = Ks + BKV * QP;        // BKV * HD
    float* Ps = Vs + BKV * HD;        // BQ * PP

    const int qt  = blockIdx.x;       // 0..31
    const int bh  = blockIdx.y;       // 0..63
    const int b   = bh >> 5;
    const int h   = bh & 31;
    const int tid = threadIdx.x;
    const int ty  = tid >> 4;
    const int tx  = tid & 15;

    const float scale = 0.10206207261596577f;  // 96^-0.5

    const float* qbase = qkv + (size_t)b * LL * OPSZ + h * HD;
    const float* kbase = qbase + 3072;
    const float* vbase = qbase + 6144;

    // load Q tile (scaled)
    for (int idx = tid; idx < BQ * HD; idx += 256) {
        int r = idx / HD, d = idx % HD;
        Qs[r * QP + d] = qbase[(size_t)(qt * BQ + r) * OPSZ + d] * scale;
    }

    float m[4], l[4], acc[4][6];
#pragma unroll
    for (int i = 0; i < 4; i++) {
        m[i] = -INFINITY; l[i] = 0.0f;
#pragma unroll
        for (int j = 0; j < 6; j++) acc[i][j] = 0.0f;
    }

    __syncthreads();

    for (int kb = 0; kb <= qt; kb++) {
        // barrier: previous iteration's PV reads of Ks/Vs/Ps must finish
        __syncthreads();
        for (int idx = tid; idx < BKV * HD; idx += 256) {
            int r = idx / HD, d = idx % HD;
            Ks[r * QP + d] = kbase[(size_t)(kb * BKV + r) * OPSZ + d];
            Vs[r * HD + d] = vbase[(size_t)(kb * BKV + r) * OPSZ + d];
        }
        __syncthreads();

        // S = Q K^T  (4x4 per thread)
        float s[4][4];
#pragma unroll
        for (int i = 0; i < 4; i++)
#pragma unroll
            for (int j = 0; j < 4; j++) s[i][j] = 0.0f;

#pragma unroll 4
        for (int kk = 0; kk < HD; kk++) {
            float qv[4], kv[4];
#pragma unroll
            for (int i = 0; i < 4; i++) qv[i] = Qs[(ty * 4 + i) * QP + kk];
#pragma unroll
            for (int j = 0; j < 4; j++) kv[j] = Ks[(tx * 4 + j) * QP + kk];
#pragma unroll
            for (int i = 0; i < 4; i++)
#pragma unroll
                for (int j = 0; j < 4; j++)
                    s[i][j] = fmaf(qv[i], kv[j], s[i][j]);
        }

        // causal mask only on diagonal block
        if (kb == qt) {
#pragma unroll
            for (int i = 0; i < 4; i++) {
                int r = ty * 4 + i;
#pragma unroll
                for (int j = 0; j < 4; j++) {
                    int c = tx * 4 + j;
                    if (c > r) s[i][j] = -INFINITY;
                }
            }
        }

        // online softmax per row (reduce across 16 tx lanes)
#pragma unroll
        for (int i = 0; i < 4; i++) {
            float mx = fmaxf(fmaxf(s[i][0], s[i][1]), fmaxf(s[i][2], s[i][3]));
#pragma unroll
            for (int off = 8; off >= 1; off >>= 1)
                mx = fmaxf(mx, __shfl_xor_sync(0xffffffffu, mx, off));
            float mnew  = fmaxf(m[i], mx);
            float alpha = __expf(m[i] - mnew);
            float psum = 0.0f;
            int r = ty * 4 + i;
#pragma unroll
            for (int j = 0; j < 4; j++) {
                float p = __expf(s[i][j] - mnew);
                Ps[r * PP + tx * 4 + j] = p;
                psum += p;
            }
#pragma unroll
            for (int off = 8; off >= 1; off >>= 1)
                psum += __shfl_xor_sync(0xffffffffu, psum, off);
            l[i] = l[i] * alpha + psum;
            m[i] = mnew;
#pragma unroll
            for (int j = 0; j < 6; j++) acc[i][j] *= alpha;
        }
        __syncthreads();

        // O += P V   (4 rows x 6 cols per thread)
#pragma unroll 4
        for (int kk = 0; kk < BKV; kk++) {
            float vv[6];
#pragma unroll
            for (int j = 0; j < 6; j++) vv[j] = Vs[kk * HD + tx * 6 + j];
#pragma unroll
            for (int i = 0; i < 4; i++) {
                float p = Ps[(ty * 4 + i) * PP + kk];
#pragma unroll
                for (int j = 0; j < 6; j++)
                    acc[i][j] = fmaf(p, vv[j], acc[i][j]);
            }
        }
    }

    // write [b, l, h*96 + d]
#pragma unroll
    for (int i = 0; i < 4; i++) {
        int lrow = qt * BQ + ty * 4 + i;
        float inv = 1.0f / l[i];
        float* op = out + (size_t)(b * LL + lrow) * HIDDEN + h * HD + tx * 6;
#pragma unroll
        for (int j = 0; j < 6; j++) op[j] = acc[i][j] * inv;
    }
}

// ---------------- launch ----------------
extern "C" void kernel_launch(void* const* d_in, const int* in_sizes, int n_in,
                              void* d_out, int out_size)
{
    const float* x    = (const float*)d_in[0];
    const float* Wqkv = (const float*)d_in[1];
    const float* Wo   = (const float*)d_in[2];
    float* out = (float*)d_out;

    float* qkv;  cudaGetSymbolAddress((void**)&qkv,  g_qkv);
    float* attn; cudaGetSymbolAddress((void**)&attn, g_attn);

    // opt-in to >48KB dynamic smem for flash kernel (idempotent, not a stream op)
    static const int flash_smem = FLASH_SMEM_FLOATS * (int)sizeof(float);
    cudaFuncSetAttribute(flash_kernel,
                         cudaFuncAttributeMaxDynamicSharedMemorySize, flash_smem);

    // 1) QKV = x @ Wqkv^T : [4096, 9216]
    {
        dim3 grid(OPSZ / 128, MTOK / 128);
        gemm_nt_kernel<<<grid, 256>>>(x, Wqkv, qkv, MTOK, OPSZ, HIDDEN);
    }
    // 2) RoPE
    {
        int n1 = LL * 48;
        rope_table_kernel<<<(n1 + 255) / 256, 256>>>();
        int n2 = MTOK * NH * 48;
        rope_apply_kernel<<<(n2 + 255) / 256, 256>>>();
    }
    // 3) flash attention -> attn [4096, 3072]
    {
        dim3 grid(LL / BQ, BB * NH);
        flash_kernel<<<grid, 256, flash_smem>>>(qkv, attn);
    }
    // 4) out = attn @ Wo^T : [4096, 3072]
    {
        dim3 grid(HIDDEN / 128, MTOK / 128);
        gemm_nt_kernel<<<grid, 256>>>(attn, Wo, out, MTOK, HIDDEN, HIDDEN);
    }
}

// round 3
// speedup vs baseline: 1.0025x; 1.0015x over previous
#include <cuda_runtime.h>
#include <math.h>

#define HIDDEN 3072
#define NH     32
#define HD     96
#define OPSZ   9216   // 32*96 + 2*32*96
#define BB     2
#define LL     2048
#define MTOK   4096   // BB*LL

// ---------------- scratch (static device globals; no allocation) ----------------
__device__ float g_qkv[(size_t)MTOK * OPSZ];    // [token, 9216] : q | k | v
__device__ float g_attn[(size_t)MTOK * HIDDEN]; // [token, 3072]
__device__ float g_cos[LL * 48];
__device__ float g_sin[LL * 48];

// ---------------- RoPE table (double precision phases) ----------------
__global__ void rope_table_kernel() {
    int idx = blockIdx.x * blockDim.x + threadIdx.x;
    if (idx >= LL * 48) return;
    int i = idx % 48;
    int l = idx / 48;
    // inv_freq = 10000^{-i/48}; scaling = sqrt(1 + ln(32)/ln(4096)) = sqrt(17/12)
    double invf = exp(-(double)i / 48.0 * log(10000.0));
    double ang  = (double)l * invf;
    double S    = sqrt(17.0 / 12.0);
    double s, c;
    sincos(ang, &s, &c);
    g_cos[idx] = (float)(c * S);
    g_sin[idx] = (float)(s * S);
}

// ---------------- RoPE apply (in-place on q,k slices of g_qkv) ----------------
__global__ void rope_apply_kernel() {
    int idx = blockIdx.x * blockDim.x + threadIdx.x;
    const int total = MTOK * NH * 48;
    if (idx >= total) return;
    int i = idx % 48;
    int h = (idx / 48) % NH;
    int t = idx / (48 * NH);       // token 0..4095
    int l = t & (LL - 1);
    float c = g_cos[l * 48 + i];
    float s = g_sin[l * 48 + i];
    float* qb = g_qkv + (size_t)t * OPSZ + h * HD;
    float q0 = qb[i], q1 = qb[i + 48];
    qb[i]      = q0 * c - q1 * s;
    qb[i + 48] = q1 * c + q0 * s;
    float* kb = qb + 3072;
    float k0 = kb[i], k1 = kb[i + 48];
    kb[i]      = k0 * c - k1 * s;
    kb[i + 48] = k1 * c + k0 * s;
}

// ---------------- tiled SGEMM: C[M,N] = A[M,K] * B[N,K]^T ----------------
// BM=BN=128, BK=8, 256 threads, 8x8 per thread (split 4+4 at +64 offsets).
__global__ __launch_bounds__(256) void gemm_nt_kernel(
    const float* __restrict__ A, const float* __restrict__ Bm,
    float* __restrict__ C, int M, int N, int K)
{
    __shared__ float As[8][128];
    __shared__ float Bs[8][128];
    const int tid = threadIdx.x;
    const int bm = blockIdx.y * 128;
    const int bn = blockIdx.x * 128;
    const int ry = tid >> 4;          // 0..15
    const int rx = tid & 15;          // 0..15
    const int lrow = tid >> 1;        // 0..127
    const int lcol = (tid & 1) << 2;  // 0 or 4

    const float* Ap = A  + (size_t)(bm + lrow) * K + lcol;
    const float* Bp = Bm + (size_t)(bn + lrow) * K + lcol;

    float acc[8][8];
#pragma unroll
    for (int i = 0; i < 8; i++)
#pragma unroll
        for (int j = 0; j < 8; j++) acc[i][j] = 0.0f;

    for (int kb = 0; kb < K; kb += 8) {
        float4 a = *(const float4*)(Ap + kb);
        float4 b = *(const float4*)(Bp + kb);
        As[lcol + 0][lrow] = a.x; As[lcol + 1][lrow] = a.y;
        As[lcol + 2][lrow] = a.z; As[lcol + 3][lrow] = a.w;
        Bs[lcol + 0][lrow] = b.x; Bs[lcol + 1][lrow] = b.y;
        Bs[lcol + 2][lrow] = b.z; Bs[lcol + 3][lrow] = b.w;
        __syncthreads();
#pragma unroll
        for (int kk = 0; kk < 8; kk++) {
            float4 a0 = *(const float4*)&As[kk][ry * 4];
            float4 a1 = *(const float4*)&As[kk][ry * 4 + 64];
            float4 b0 = *(const float4*)&Bs[kk][rx * 4];
            float4 b1 = *(const float4*)&Bs[kk][rx * 4 + 64];
            float av[8] = {a0.x, a0.y, a0.z, a0.w, a1.x, a1.y, a1.z, a1.w};
            float bv[8] = {b0.x, b0.y, b0.z, b0.w, b1.x, b1.y, b1.z, b1.w};
#pragma unroll
            for (int i = 0; i < 8; i++)
#pragma unroll
                for (int j = 0; j < 8; j++)
                    acc[i][j] = fmaf(av[i], bv[j], acc[i][j]);
        }
        __syncthreads();
    }

#pragma unroll
    for (int ih = 0; ih < 2; ih++)
#pragma unroll
        for (int i = 0; i < 4; i++) {
            int row = bm + ih * 64 + ry * 4 + i;
            float* Cp = C + (size_t)row * N + bn;
            int ai = ih * 4 + i;
            *(float4*)(Cp + rx * 4) =
                make_float4(acc[ai][0], acc[ai][1], acc[ai][2], acc[ai][3]);
            *(float4*)(Cp + 64 + rx * 4) =
                make_float4(acc[ai][4], acc[ai][5], acc[ai][6], acc[ai][7]);
        }
}

// ---------------- fp32 flash attention ----------------
// grid: (32 q-tiles, 64 b*h). block: 256 threads (16x16).
// Thread (ty,tx): S tile rows ty*4..+3, cols tx*4..+3 ; O tile rows ty*4..+3, cols tx*6..+5.
#define BQ 64
#define BKV 64
#define QP 97   // pitch for Q/K rows (96 data + 1 pad -> bank stride 1)
#define PP 65   // pitch for P rows
#define FLASH_SMEM_FLOATS (BQ*QP + BKV*QP + BKV*HD + BQ*PP)

__global__ __launch_bounds__(256) void flash_kernel(
    const float* __restrict__ qkv, float* __restrict__ out)
{
    extern __shared__ float sm[];
    float* Qs = sm;                   // BQ * QP
    float* Ks = Qs + BQ * QP;         // BKV * QP
    float* Vs = Ks + BKV * QP;        // BKV * HD
    float* Ps = Vs + BKV * HD;        // BQ * PP

    const int qt  = blockIdx.x;       // 0..31
    const int bh  = blockIdx.y;       // 0..63
    const int b   = bh >> 5;
    const int h   = bh & 31;
    const int tid = threadIdx.x;
    const int ty  = tid >> 4;
    const int tx  = tid & 15;

    const float scale = 0.10206207261596577f;  // 96^-0.5

    const float* qbase = qkv + (size_t)b * LL * OPSZ + h * HD;
    const float* kbase = qbase + 3072;
    const float* vbase = qbase + 6144;

    // load Q tile (scaled)
    for (int idx = tid; idx < BQ * HD; idx += 256) {
        int r = idx / HD, d = idx % HD;
        Qs[r * QP + d] = qbase[(size_t)(qt * BQ + r) * OPSZ + d] * scale;
    }

    float m[4], l[4], acc[4][6];
#pragma unroll
    for (int i = 0; i < 4; i++) {
        m[i] = -INFINITY; l[i] = 0.0f;
#pragma unroll
        for (int j = 0; j < 6; j++) acc[i][j] = 0.0f;
    }

    __syncthreads();

    for (int kb = 0; kb <= qt; kb++) {
        // barrier: previous iteration's PV reads of Ks/Vs/Ps must finish
        __syncthreads();
        for (int idx = tid; idx < BKV * HD; idx += 256) {
            int r = idx / HD, d = idx % HD;
            Ks[r * QP + d] = kbase[(size_t)(kb * BKV + r) * OPSZ + d];
            Vs[r * HD + d] = vbase[(size_t)(kb * BKV + r) * OPSZ + d];
        }
        __syncthreads();

        // S = Q K^T  (4x4 per thread)
        float s[4][4];
#pragma unroll
        for (int i = 0; i < 4; i++)
#pragma unroll
            for (int j = 0; j < 4; j++) s[i][j] = 0.0f;

#pragma unroll 4
        for (int kk = 0; kk < HD; kk++) {
            float qv[4], kv[4];
#pragma unroll
            for (int i = 0; i < 4; i++) qv[i] = Qs[(ty * 4 + i) * QP + kk];
#pragma unroll
            for (int j = 0; j < 4; j++) kv[j] = Ks[(tx * 4 + j) * QP + kk];
#pragma unroll
            for (int i = 0; i < 4; i++)
#pragma unroll
                for (int j = 0; j < 4; j++)
                    s[i][j] = fmaf(qv[i], kv[j], s[i][j]);
        }

        // causal mask only on diagonal block
        if (kb == qt) {
#pragma unroll
            for (int i = 0; i < 4; i++) {
                int r = ty * 4 + i;
#pragma unroll
                for (int j = 0; j < 4; j++) {
                    int c = tx * 4 + j;
                    if (c > r) s[i][j] = -INFINITY;
                }
            }
        }

        // online softmax per row (reduce across 16 tx lanes)
#pragma unroll
        for (int i = 0; i < 4; i++) {
            float mx = fmaxf(fmaxf(s[i][0], s[i][1]), fmaxf(s[i][2], s[i][3]));
#pragma unroll
            for (int off = 8; off >= 1; off >>= 1)
                mx = fmaxf(mx, __shfl_xor_sync(0xffffffffu, mx, off));
            float mnew  = fmaxf(m[i], mx);
            float alpha = __expf(m[i] - mnew);
            float psum = 0.0f;
            int r = ty * 4 + i;
#pragma unroll
            for (int j = 0; j < 4; j++) {
                float p = __expf(s[i][j] - mnew);
                Ps[r * PP + tx * 4 + j] = p;
                psum += p;
            }
#pragma unroll
            for (int off = 8; off >= 1; off >>= 1)
                psum += __shfl_xor_sync(0xffffffffu, psum, off);
            l[i] = l[i] * alpha + psum;
            m[i] = mnew;
#pragma unroll
            for (int j = 0; j < 6; j++) acc[i][j] *= alpha;
        }
        __syncthreads();

        // O += P V   (4 rows x 6 cols per thread)
#pragma unroll 4
        for (int kk = 0; kk < BKV; kk++) {
            float vv[6];
#pragma unroll
            for (int j = 0; j < 6; j++) vv[j] = Vs[kk * HD + tx * 6 + j];
#pragma unroll
            for (int i = 0; i < 4; i++) {
                float p = Ps[(ty * 4 + i) * PP + kk];
#pragma unroll
                for (int j = 0; j < 6; j++)
                    acc[i][j] = fmaf(p, vv[j], acc[i][j]);
            }
        }
    }

    // write [b, l, h*96 + d]
#pragma unroll
    for (int i = 0; i < 4; i++) {
        int lrow = qt * BQ + ty * 4 + i;
        float inv = 1.0f / l[i];
        float* op = out + (size_t)(b * LL + lrow) * HIDDEN + h * HD + tx * 6;
#pragma unroll
        for (int j = 0; j < 6; j++) op[j] = acc[i][j] * inv;
    }
}

// ---------------- launch ----------------
extern "C" void kernel_launch(void* const* d_in, const int* in_sizes, int n_in,
                              void* d_out, int out_size)
{
    const float* x    = (const float*)d_in[0];
    const float* Wqkv = (const float*)d_in[1];
    const float* Wo   = (const float*)d_in[2];
    float* out = (float*)d_out;

    float* qkv;  cudaGetSymbolAddress((void**)&qkv,  g_qkv);
    float* attn; cudaGetSymbolAddress((void**)&attn, g_attn);

    // opt-in to >48KB dynamic smem for flash kernel (idempotent, not a stream op)
    static const int flash_smem = FLASH_SMEM_FLOATS * (int)sizeof(float);
    cudaFuncSetAttribute(flash_kernel,
                         cudaFuncAttributeMaxDynamicSharedMemorySize, flash_smem);

    // 1) QKV = x @ Wqkv^T : [4096, 9216]
    {
        dim3 grid(OPSZ / 128, MTOK / 128);
        gemm_nt_kernel<<<grid, 256>>>(x, Wqkv, qkv, MTOK, OPSZ, HIDDEN);
    }
    // 2) RoPE
    {
        int n1 = LL * 48;
        rope_table_kernel<<<(n1 + 255) / 256, 256>>>();
        int n2 = MTOK * NH * 48;
        rope_apply_kernel<<<(n2 + 255) / 256, 256>>>();
    }
    // 3) flash attention -> attn [4096, 3072]
    {
        dim3 grid(LL / BQ, BB * NH);
        flash_kernel<<<grid, 256, flash_smem>>>(qkv, attn);
    }
    // 4) out = attn @ Wo^T : [4096, 3072]
    {
        dim3 grid(HIDDEN / 128, MTOK / 128);
        gemm_nt_kernel<<<grid, 256>>>(attn, Wo, out, MTOK, HIDDEN, HIDDEN);
    }
}

// round 4
// speedup vs baseline: 1.7934x; 1.7889x over previous
#include <cuda_runtime.h>
#include <math.h>
#include <stdint.h>

#define HIDDEN 3072
#define NH     32
#define HD     96
#define OPSZ   9216   // 32*96 + 2*32*96
#define BB     2
#define LL     2048
#define MTOK   4096   // BB*LL

// ---------------- scratch (static device globals; no allocation) ----------------
__device__ float g_qkv[(size_t)MTOK * OPSZ];    // [token, 9216] : q | k | v
__device__ float g_attn[(size_t)MTOK * HIDDEN]; // [token, 3072]
__device__ float g_cos[LL * 48];
__device__ float g_sin[LL * 48];

// ---------------- RoPE table (double precision phases) ----------------
__global__ void rope_table_kernel() {
    int idx = blockIdx.x * blockDim.x + threadIdx.x;
    if (idx >= LL * 48) return;
    int i = idx % 48;
    int l = idx / 48;
    double invf = exp(-(double)i / 48.0 * log(10000.0));
    double ang  = (double)l * invf;
    double S    = sqrt(17.0 / 12.0);   // sqrt(1 + ln32/ln4096)
    double s, c;
    sincos(ang, &s, &c);
    g_cos[idx] = (float)(c * S);
    g_sin[idx] = (float)(s * S);
}

// ---------------- RoPE apply (in-place on q,k slices of g_qkv) ----------------
__global__ void rope_apply_kernel() {
    int idx = blockIdx.x * blockDim.x + threadIdx.x;
    const int total = MTOK * NH * 48;
    if (idx >= total) return;
    int i = idx % 48;
    int h = (idx / 48) % NH;
    int t = idx / (48 * NH);
    int l = t & (LL - 1);
    float c = g_cos[l * 48 + i];
    float s = g_sin[l * 48 + i];
    float* qb = g_qkv + (size_t)t * OPSZ + h * HD;
    float q0 = qb[i], q1 = qb[i + 48];
    qb[i]      = q0 * c - q1 * s;
    qb[i + 48] = q1 * c + q0 * s;
    float* kb = qb + 3072;
    float k0 = kb[i], k1 = kb[i + 48];
    kb[i]      = k0 * c - k1 * s;
    kb[i + 48] = k1 * c + k0 * s;
}

// ---------------- TF32 tensor-core GEMM: C[M,N] = A[M,K] * B[N,K]^T ----------------
// BM=BN=128, BK=16. 256 threads = 8 warps in 2(M) x 4(N); warp tile 64x32.
// mma.sync.aligned.m16n8k8.row.col.f32.tf32.tf32.f32, 4x4 mma tiles per warp.
// Smem staged k-major with pitch 136 floats -> fragment-read bank = 8k+g (conflict-free).

#define GPITCH 136

__device__ __forceinline__ float tf32r(float x) {
    uint32_t u;
    asm("cvt.rna.tf32.f32 %0, %1;" : "=r"(u) : "f"(x));
    return __uint_as_float(u);
}

__device__ __forceinline__ void mma_tf32(
    float& d0, float& d1, float& d2, float& d3,
    uint32_t a0, uint32_t a1, uint32_t a2, uint32_t a3,
    uint32_t b0, uint32_t b1)
{
    asm volatile(
        "mma.sync.aligned.m16n8k8.row.col.f32.tf32.tf32.f32 "
        "{%0,%1,%2,%3}, {%4,%5,%6,%7}, {%8,%9}, {%0,%1,%2,%3};"
        : "+f"(d0), "+f"(d1), "+f"(d2), "+f"(d3)
        : "r"(a0), "r"(a1), "r"(a2), "r"(a3), "r"(b0), "r"(b1));
}

__global__ __launch_bounds__(256) void gemm_tf32_nt_kernel(
    const float* __restrict__ A, const float* __restrict__ Bm,
    float* __restrict__ C, int M, int N, int K)
{
    __shared__ float As[16][GPITCH];
    __shared__ float Bs[16][GPITCH];

    const int tid  = threadIdx.x;
    const int w    = tid >> 5;
    const int lane = tid & 31;
    const int wm   = w >> 2;        // 0..1
    const int wn   = w & 3;         // 0..3
    const int g    = lane >> 2;     // 0..7
    const int tk   = lane & 3;      // 0..3
    const int bm   = blockIdx.y * 128;
    const int bn   = blockIdx.x * 128;

    // global staging: thread -> (row = tid/4 [+64], k-chunk = (tid%4)*4)
    const int lr = tid >> 2;          // 0..63
    const int lc = (tid & 3) << 2;    // 0,4,8,12

    const float* Ap  = A  + (size_t)(bm + lr) * K + lc;
    const float* Ap2 = Ap + (size_t)64 * K;
    const float* Bp  = Bm + (size_t)(bn + lr) * K + lc;
    const float* Bp2 = Bp + (size_t)64 * K;

    float acc[4][4][4];
#pragma unroll
    for (int mi = 0; mi < 4; mi++)
#pragma unroll
        for (int ni = 0; ni < 4; ni++)
#pragma unroll
            for (int r = 0; r < 4; r++) acc[mi][ni][r] = 0.0f;

    // prefetch first tile
    float4 ra0 = *(const float4*)(Ap);
    float4 ra1 = *(const float4*)(Ap2);
    float4 rb0 = *(const float4*)(Bp);
    float4 rb1 = *(const float4*)(Bp2);

    for (int kb = 0; kb < K; kb += 16) {
        // store (tf32-rounded) to k-major smem
        As[lc + 0][lr]      = tf32r(ra0.x);
        As[lc + 1][lr]      = tf32r(ra0.y);
        As[lc + 2][lr]      = tf32r(ra0.z);
        As[lc + 3][lr]      = tf32r(ra0.w);
        As[lc + 0][lr + 64] = tf32r(ra1.x);
        As[lc + 1][lr + 64] = tf32r(ra1.y);
        As[lc + 2][lr + 64] = tf32r(ra1.z);
        As[lc + 3][lr + 64] = tf32r(ra1.w);
        Bs[lc + 0][lr]      = tf32r(rb0.x);
        Bs[lc + 1][lr]      = tf32r(rb0.y);
        Bs[lc + 2][lr]      = tf32r(rb0.z);
        Bs[lc + 3][lr]      = tf32r(rb0.w);
        Bs[lc + 0][lr + 64] = tf32r(rb1.x);
        Bs[lc + 1][lr + 64] = tf32r(rb1.y);
        Bs[lc + 2][lr + 64] = tf32r(rb1.z);
        Bs[lc + 3][lr + 64] = tf32r(rb1.w);
        __syncthreads();

        // prefetch next tile (overlaps with compute below)
        if (kb + 16 < K) {
            ra0 = *(const float4*)(Ap  + kb + 16);
            ra1 = *(const float4*)(Ap2 + kb + 16);
            rb0 = *(const float4*)(Bp  + kb + 16);
            rb1 = *(const float4*)(Bp2 + kb + 16);
        }

#pragma unroll
        for (int ks = 0; ks < 2; ks++) {
            const int k0 = ks * 8;
            uint32_t afr[4][4];
            uint32_t bfr[4][2];
#pragma unroll
            for (int mi = 0; mi < 4; mi++) {
                int row = wm * 64 + mi * 16 + g;
                afr[mi][0] = __float_as_uint(As[k0 + tk][row]);
                afr[mi][1] = __float_as_uint(As[k0 + tk][row + 8]);
                afr[mi][2] = __float_as_uint(As[k0 + tk + 4][row]);
                afr[mi][3] = __float_as_uint(As[k0 + tk + 4][row + 8]);
            }
#pragma unroll
            for (int ni = 0; ni < 4; ni++) {
                int col = wn * 32 + ni * 8 + g;
                bfr[ni][0] = __float_as_uint(Bs[k0 + tk][col]);
                bfr[ni][1] = __float_as_uint(Bs[k0 + tk + 4][col]);
            }
#pragma unroll
            for (int mi = 0; mi < 4; mi++)
#pragma unroll
                for (int ni = 0; ni < 4; ni++)
                    mma_tf32(acc[mi][ni][0], acc[mi][ni][1],
                             acc[mi][ni][2], acc[mi][ni][3],
                             afr[mi][0], afr[mi][1], afr[mi][2], afr[mi][3],
                             bfr[ni][0], bfr[ni][1]);
        }
        __syncthreads();
    }

    // epilogue: c0:(g,2tk) c1:(g,2tk+1) c2:(g+8,2tk) c3:(g+8,2tk+1)
#pragma unroll
    for (int mi = 0; mi < 4; mi++) {
#pragma unroll
        for (int ni = 0; ni < 4; ni++) {
            int row = bm + wm * 64 + mi * 16 + g;
            int col = bn + wn * 32 + ni * 8 + tk * 2;
            *(float2*)(C + (size_t)row * N + col) =
                make_float2(acc[mi][ni][0], acc[mi][ni][1]);
            *(float2*)(C + (size_t)(row + 8) * N + col) =
                make_float2(acc[mi][ni][2], acc[mi][ni][3]);
        }
    }
}

// ---------------- fp32 flash attention (unchanged) ----------------
#define BQ 64
#define BKV 64
#define QP 97
#define PP 65
#define FLASH_SMEM_FLOATS (BQ*QP + BKV*QP + BKV*HD + BQ*PP)

__global__ __launch_bounds__(256) void flash_kernel(
    const float* __restrict__ qkv, float* __restrict__ out)
{
    extern __shared__ float sm[];
    float* Qs = sm;
    float* Ks = Qs + BQ * QP;
    float* Vs = Ks + BKV * QP;
    float* Ps = Vs + BKV * HD;

    const int qt  = blockIdx.x;
    const int bh  = blockIdx.y;
    const int b   = bh >> 5;
    const int h   = bh & 31;
    const int tid = threadIdx.x;
    const int ty  = tid >> 4;
    const int tx  = tid & 15;

    const float scale = 0.10206207261596577f;

    const float* qbase = qkv + (size_t)b * LL * OPSZ + h * HD;
    const float* kbase = qbase + 3072;
    const float* vbase = qbase + 6144;

    for (int idx = tid; idx < BQ * HD; idx += 256) {
        int r = idx / HD, d = idx % HD;
        Qs[r * QP + d] = qbase[(size_t)(qt * BQ + r) * OPSZ + d] * scale;
    }

    float m[4], l[4], acc[4][6];
#pragma unroll
    for (int i = 0; i < 4; i++) {
        m[i] = -INFINITY; l[i] = 0.0f;
#pragma unroll
        for (int j = 0; j < 6; j++) acc[i][j] = 0.0f;
    }

    __syncthreads();

    for (int kb = 0; kb <= qt; kb++) {
        __syncthreads();
        for (int idx = tid; idx < BKV * HD; idx += 256) {
            int r = idx / HD, d = idx % HD;
            Ks[r * QP + d] = kbase[(size_t)(kb * BKV + r) * OPSZ + d];
            Vs[r * HD + d] = vbase[(size_t)(kb * BKV + r) * OPSZ + d];
        }
        __syncthreads();

        float s[4][4];
#pragma unroll
        for (int i = 0; i < 4; i++)
#pragma unroll
            for (int j = 0; j < 4; j++) s[i][j] = 0.0f;

#pragma unroll 4
        for (int kk = 0; kk < HD; kk++) {
            float qv[4], kv[4];
#pragma unroll
            for (int i = 0; i < 4; i++) qv[i] = Qs[(ty * 4 + i) * QP + kk];
#pragma unroll
            for (int j = 0; j < 4; j++) kv[j] = Ks[(tx * 4 + j) * QP + kk];
#pragma unroll
            for (int i = 0; i < 4; i++)
#pragma unroll
                for (int j = 0; j < 4; j++)
                    s[i][j] = fmaf(qv[i], kv[j], s[i][j]);
        }

        if (kb == qt) {
#pragma unroll
            for (int i = 0; i < 4; i++) {
                int r = ty * 4 + i;
#pragma unroll
                for (int j = 0; j < 4; j++) {
                    int c = tx * 4 + j;
                    if (c > r) s[i][j] = -INFINITY;
                }
            }
        }

#pragma unroll
        for (int i = 0; i < 4; i++) {
            float mx = fmaxf(fmaxf(s[i][0], s[i][1]), fmaxf(s[i][2], s[i][3]));
#pragma unroll
            for (int off = 8; off >= 1; off >>= 1)
                mx = fmaxf(mx, __shfl_xor_sync(0xffffffffu, mx, off));
            float mnew  = fmaxf(m[i], mx);
            float alpha = __expf(m[i] - mnew);
            float psum = 0.0f;
            int r = ty * 4 + i;
#pragma unroll
            for (int j = 0; j < 4; j++) {
                float p = __expf(s[i][j] - mnew);
                Ps[r * PP + tx * 4 + j] = p;
                psum += p;
            }
#pragma unroll
            for (int off = 8; off >= 1; off >>= 1)
                psum += __shfl_xor_sync(0xffffffffu, psum, off);
            l[i] = l[i] * alpha + psum;
            m[i] = mnew;
#pragma unroll
            for (int j = 0; j < 6; j++) acc[i][j] *= alpha;
        }
        __syncthreads();

#pragma unroll 4
        for (int kk = 0; kk < BKV; kk++) {
            float vv[6];
#pragma unroll
            for (int j = 0; j < 6; j++) vv[j] = Vs[kk * HD + tx * 6 + j];
#pragma unroll
            for (int i = 0; i < 4; i++) {
                float p = Ps[(ty * 4 + i) * PP + kk];
#pragma unroll
                for (int j = 0; j < 6; j++)
                    acc[i][j] = fmaf(p, vv[j], acc[i][j]);
            }
        }
    }

#pragma unroll
    for (int i = 0; i < 4; i++) {
        int lrow = qt * BQ + ty * 4 + i;
        float inv = 1.0f / l[i];
        float* op = out + (size_t)(b * LL + lrow) * HIDDEN + h * HD + tx * 6;
#pragma unroll
        for (int j = 0; j < 6; j++) op[j] = acc[i][j] * inv;
    }
}

// ---------------- launch ----------------
extern "C" void kernel_launch(void* const* d_in, const int* in_sizes, int n_in,
                              void* d_out, int out_size)
{
    const float* x    = (const float*)d_in[0];
    const float* Wqkv = (const float*)d_in[1];
    const float* Wo   = (const float*)d_in[2];
    float* out = (float*)d_out;

    float* qkv;  cudaGetSymbolAddress((void**)&qkv,  g_qkv);
    float* attn; cudaGetSymbolAddress((void**)&attn, g_attn);

    static const int flash_smem = FLASH_SMEM_FLOATS * (int)sizeof(float);
    cudaFuncSetAttribute(flash_kernel,
                         cudaFuncAttributeMaxDynamicSharedMemorySize, flash_smem);

    // 1) QKV = x @ Wqkv^T : [4096, 9216]  (TF32 tensor cores)
    {
        dim3 grid(OPSZ / 128, MTOK / 128);
        gemm_tf32_nt_kernel<<<grid, 256>>>(x, Wqkv, qkv, MTOK, OPSZ, HIDDEN);
    }
    // 2) RoPE
    {
        int n1 = LL * 48;
        rope_table_kernel<<<(n1 + 255) / 256, 256>>>();
        int n2 = MTOK * NH * 48;
        rope_apply_kernel<<<(n2 + 255) / 256, 256>>>();
    }
    // 3) flash attention -> attn [4096, 3072]
    {
        dim3 grid(LL / BQ, BB * NH);
        flash_kernel<<<grid, 256, flash_smem>>>(qkv, attn);
    }
    // 4) out = attn @ Wo^T : [4096, 3072]  (TF32 tensor cores)
    {
        dim3 grid(HIDDEN / 128, MTOK / 128);
        gemm_tf32_nt_kernel<<<grid, 256>>>(attn, Wo, out, MTOK, HIDDEN, HIDDEN);
    }
}

// round 5
// speedup vs baseline: 2.0483x; 1.1421x over previous
#include <cuda_runtime.h>
#include <math.h>
#include <stdint.h>

#define HIDDEN 3072
#define NH     32
#define HD     96
#define OPSZ   9216   // 32*96 + 2*32*96
#define BB     2
#define LL     2048
#define MTOK   4096   // BB*LL

// ---------------- scratch (static device globals; no allocation) ----------------
__device__ float g_qkv[(size_t)MTOK * OPSZ];     // [token, 9216] : q | k | v
__device__ float g_attn[(size_t)MTOK * HIDDEN];  // [token, 3072] (tf32-rounded)
__device__ float g_x  [(size_t)MTOK * HIDDEN];   // tf32-rounded x
__device__ float g_wq [(size_t)OPSZ * HIDDEN];   // tf32-rounded Wqkv
__device__ float g_wo [(size_t)HIDDEN * HIDDEN]; // tf32-rounded Wo
__device__ float g_cos[LL * 48];
__device__ float g_sin[LL * 48];

__device__ __forceinline__ float tf32r(float x) {
    uint32_t u;
    asm("cvt.rna.tf32.f32 %0, %1;" : "=r"(u) : "f"(x));
    return __uint_as_float(u);
}

// ---------------- elementwise tf32 pre-round ----------------
__global__ void round_tf32_kernel(const float* __restrict__ in,
                                  float* __restrict__ outp, int n4) {
    int i = blockIdx.x * blockDim.x + threadIdx.x;
    if (i >= n4) return;
    float4 v = ((const float4*)in)[i];
    v.x = tf32r(v.x); v.y = tf32r(v.y); v.z = tf32r(v.z); v.w = tf32r(v.w);
    ((float4*)outp)[i] = v;
}

// ---------------- RoPE table (double precision phases) ----------------
__global__ void rope_table_kernel() {
    int idx = blockIdx.x * blockDim.x + threadIdx.x;
    if (idx >= LL * 48) return;
    int i = idx % 48;
    int l = idx / 48;
    double invf = exp(-(double)i / 48.0 * log(10000.0));
    double ang  = (double)l * invf;
    double S    = sqrt(17.0 / 12.0);   // sqrt(1 + ln32/ln4096)
    double s, c;
    sincos(ang, &s, &c);
    g_cos[idx] = (float)(c * S);
    g_sin[idx] = (float)(s * S);
}

// ---------------- RoPE apply (in-place on q,k slices of g_qkv) ----------------
__global__ void rope_apply_kernel() {
    int idx = blockIdx.x * blockDim.x + threadIdx.x;
    const int total = MTOK * NH * 48;
    if (idx >= total) return;
    int i = idx % 48;
    int h = (idx / 48) % NH;
    int t = idx / (48 * NH);
    int l = t & (LL - 1);
    float c = g_cos[l * 48 + i];
    float s = g_sin[l * 48 + i];
    float* qb = g_qkv + (size_t)t * OPSZ + h * HD;
    float q0 = qb[i], q1 = qb[i + 48];
    qb[i]      = q0 * c - q1 * s;
    qb[i + 48] = q1 * c + q0 * s;
    float* kb = qb + 3072;
    float k0 = kb[i], k1 = kb[i + 48];
    kb[i]      = k0 * c - k1 * s;
    kb[i + 48] = k1 * c + k0 * s;
}

// ---------------- TF32 tensor-core GEMM: C[M,N] = A[M,K] * B[N,K]^T ----------------
// BM=128, BN=256, BK=16. 256 threads = 8 warps in 2(M) x 4(N); warp tile 64x64.
// cp.async double-buffered smem, row-major pitch 20 (conflict-free fragment LDS).
// Inputs must already be tf32-rounded.

#define APITCH 20
#define BPITCH 20
#define ASTAGE (128 * APITCH)
#define BSTAGE (256 * BPITCH)
#define GEMM_SMEM_BYTES ((2 * ASTAGE + 2 * BSTAGE) * 4)

__device__ __forceinline__ void cp16(uint32_t dst, const float* src) {
    asm volatile("cp.async.cg.shared.global [%0], [%1], 16;\n" :: "r"(dst), "l"(src));
}

__device__ __forceinline__ void mma_tf32(
    float& d0, float& d1, float& d2, float& d3,
    uint32_t a0, uint32_t a1, uint32_t a2, uint32_t a3,
    uint32_t b0, uint32_t b1)
{
    asm volatile(
        "mma.sync.aligned.m16n8k8.row.col.f32.tf32.tf32.f32 "
        "{%0,%1,%2,%3}, {%4,%5,%6,%7}, {%8,%9}, {%0,%1,%2,%3};"
        : "+f"(d0), "+f"(d1), "+f"(d2), "+f"(d3)
        : "r"(a0), "r"(a1), "r"(a2), "r"(a3), "r"(b0), "r"(b1));
}

__global__ __launch_bounds__(256) void gemm_tf32_nt_kernel(
    const float* __restrict__ A, const float* __restrict__ Bm,
    float* __restrict__ C, int M, int N, int K)
{
    extern __shared__ float sm[];
    float* Asm = sm;                   // [2][ASTAGE]
    float* Bsm = sm + 2 * ASTAGE;      // [2][BSTAGE]

    const int tid  = threadIdx.x;
    const int w    = tid >> 5;
    const int lane = tid & 31;
    const int wm   = w >> 2;           // 0..1  (M offset 64)
    const int wn   = w & 3;            // 0..3  (N offset 64)
    const int g    = lane >> 2;        // 0..7
    const int tk   = lane & 3;         // 0..3
    const int bm   = blockIdx.y * 128;
    const int bn   = blockIdx.x * 256;

    // copy assignment: thread t -> A row t/2, B rows t/2 and t/2+128,
    // k-chunk base (t&1)*8, two 16B chunks each (+0, +4 floats)
    const int crow = tid >> 1;
    const int ckc  = (tid & 1) << 3;

    const float* Ap  = A  + (size_t)(bm + crow) * K + ckc;
    const float* Bp  = Bm + (size_t)(bn + crow) * K + ckc;
    const float* Bp2 = Bp + (size_t)128 * K;

    uint32_t sA = (uint32_t)__cvta_generic_to_shared(Asm)
                + (uint32_t)(crow * APITCH + ckc) * 4u;
    uint32_t sB = (uint32_t)__cvta_generic_to_shared(Bsm)
                + (uint32_t)(crow * BPITCH + ckc) * 4u;

    float acc[4][8][4];
#pragma unroll
    for (int mi = 0; mi < 4; mi++)
#pragma unroll
        for (int ni = 0; ni < 8; ni++)
#pragma unroll
            for (int r = 0; r < 4; r++) acc[mi][ni][r] = 0.0f;

    // preload stage 0
    {
        cp16(sA, Ap);                      cp16(sA + 16, Ap + 4);
        cp16(sB, Bp);                      cp16(sB + 16, Bp + 4);
        cp16(sB + 128u * BPITCH * 4u, Bp2); cp16(sB + 128u * BPITCH * 4u + 16, Bp2 + 4);
        asm volatile("cp.async.commit_group;\n" ::: "memory");
    }

    int s = 0;
    for (int kb = 0; kb < K; kb += 16) {
        const bool more = (kb + 16 < K);
        if (more) {
            uint32_t dA = sA + (uint32_t)((s ^ 1) * ASTAGE) * 4u;
            uint32_t dB = sB + (uint32_t)((s ^ 1) * BSTAGE) * 4u;
            const float* a0 = Ap  + kb + 16;
            const float* b0 = Bp  + kb + 16;
            const float* b1 = Bp2 + kb + 16;
            cp16(dA, a0);                       cp16(dA + 16, a0 + 4);
            cp16(dB, b0);                       cp16(dB + 16, b0 + 4);
            cp16(dB + 128u * BPITCH * 4u, b1);  cp16(dB + 128u * BPITCH * 4u + 16, b1 + 4);
            asm volatile("cp.async.commit_group;\n" ::: "memory");
            asm volatile("cp.async.wait_group 1;\n" ::: "memory");
        } else {
            asm volatile("cp.async.wait_group 0;\n" ::: "memory");
        }
        __syncthreads();

        const float* Ac = Asm + s * ASTAGE;
        const float* Bc = Bsm + s * BSTAGE;
#pragma unroll
        for (int ks = 0; ks < 2; ks++) {
            const int k0 = ks * 8;
            uint32_t afr[4][4];
            uint32_t bfr[8][2];
#pragma unroll
            for (int mi = 0; mi < 4; mi++) {
                int r = wm * 64 + mi * 16 + g;
                afr[mi][0] = __float_as_uint(Ac[r * APITCH + k0 + tk]);
                afr[mi][1] = __float_as_uint(Ac[(r + 8) * APITCH + k0 + tk]);
                afr[mi][2] = __float_as_uint(Ac[r * APITCH + k0 + tk + 4]);
                afr[mi][3] = __float_as_uint(Ac[(r + 8) * APITCH + k0 + tk + 4]);
            }
#pragma unroll
            for (int ni = 0; ni < 8; ni++) {
                int c = wn * 64 + ni * 8 + g;
                bfr[ni][0] = __float_as_uint(Bc[c * BPITCH + k0 + tk]);
                bfr[ni][1] = __float_as_uint(Bc[c * BPITCH + k0 + tk + 4]);
            }
#pragma unroll
            for (int mi = 0; mi < 4; mi++)
#pragma unroll
                for (int ni = 0; ni < 8; ni++)
                    mma_tf32(acc[mi][ni][0], acc[mi][ni][1],
                             acc[mi][ni][2], acc[mi][ni][3],
                             afr[mi][0], afr[mi][1], afr[mi][2], afr[mi][3],
                             bfr[ni][0], bfr[ni][1]);
        }
        __syncthreads();
        s ^= 1;
    }

    // epilogue: c0:(g,2tk) c1:(g,2tk+1) c2:(g+8,2tk) c3:(g+8,2tk+1)
#pragma unroll
    for (int mi = 0; mi < 4; mi++) {
#pragma unroll
        for (int ni = 0; ni < 8; ni++) {
            int row = bm + wm * 64 + mi * 16 + g;
            int col = bn + wn * 64 + ni * 8 + tk * 2;
            *(float2*)(C + (size_t)row * N + col) =
                make_float2(acc[mi][ni][0], acc[mi][ni][1]);
            *(float2*)(C + (size_t)(row + 8) * N + col) =
                make_float2(acc[mi][ni][2], acc[mi][ni][3]);
        }
    }
}

// ---------------- fp32 flash attention ----------------
#define BQ 64
#define BKV 64
#define QP 97
#define PP 65
#define FLASH_SMEM_FLOATS (BQ*QP + BKV*QP + BKV*HD + BQ*PP)

__global__ __launch_bounds__(256) void flash_kernel(
    const float* __restrict__ qkv, float* __restrict__ out)
{
    extern __shared__ float sm[];
    float* Qs = sm;
    float* Ks = Qs + BQ * QP;
    float* Vs = Ks + BKV * QP;
    float* Ps = Vs + BKV * HD;

    const int qt  = blockIdx.x;
    const int bh  = blockIdx.y;
    const int b   = bh >> 5;
    const int h   = bh & 31;
    const int tid = threadIdx.x;
    const int ty  = tid >> 4;
    const int tx  = tid & 15;

    const float scale = 0.10206207261596577f;

    const float* qbase = qkv + (size_t)b * LL * OPSZ + h * HD;
    const float* kbase = qbase + 3072;
    const float* vbase = qbase + 6144;

    for (int idx = tid; idx < BQ * HD; idx += 256) {
        int r = idx / HD, d = idx % HD;
        Qs[r * QP + d] = qbase[(size_t)(qt * BQ + r) * OPSZ + d] * scale;
    }

    float m[4], l[4], acc[4][6];
#pragma unroll
    for (int i = 0; i < 4; i++) {
        m[i] = -INFINITY; l[i] = 0.0f;
#pragma unroll
        for (int j = 0; j < 6; j++) acc[i][j] = 0.0f;
    }

    __syncthreads();

    for (int kb = 0; kb <= qt; kb++) {
        __syncthreads();
        for (int idx = tid; idx < BKV * HD; idx += 256) {
            int r = idx / HD, d = idx % HD;
            Ks[r * QP + d] = kbase[(size_t)(kb * BKV + r) * OPSZ + d];
            Vs[r * HD + d] = vbase[(size_t)(kb * BKV + r) * OPSZ + d];
        }
        __syncthreads();

        float s[4][4];
#pragma unroll
        for (int i = 0; i < 4; i++)
#pragma unroll
            for (int j = 0; j < 4; j++) s[i][j] = 0.0f;

#pragma unroll 4
        for (int kk = 0; kk < HD; kk++) {
            float qv[4], kv[4];
#pragma unroll
            for (int i = 0; i < 4; i++) qv[i] = Qs[(ty * 4 + i) * QP + kk];
#pragma unroll
            for (int j = 0; j < 4; j++) kv[j] = Ks[(tx * 4 + j) * QP + kk];
#pragma unroll
            for (int i = 0; i < 4; i++)
#pragma unroll
                for (int j = 0; j < 4; j++)
                    s[i][j] = fmaf(qv[i], kv[j], s[i][j]);
        }

        if (kb == qt) {
#pragma unroll
            for (int i = 0; i < 4; i++) {
                int r = ty * 4 + i;
#pragma unroll
                for (int j = 0; j < 4; j++) {
                    int c = tx * 4 + j;
                    if (c > r) s[i][j] = -INFINITY;
                }
            }
        }

#pragma unroll
        for (int i = 0; i < 4; i++) {
            float mx = fmaxf(fmaxf(s[i][0], s[i][1]), fmaxf(s[i][2], s[i][3]));
#pragma unroll
            for (int off = 8; off >= 1; off >>= 1)
                mx = fmaxf(mx, __shfl_xor_sync(0xffffffffu, mx, off));
            float mnew  = fmaxf(m[i], mx);
            float alpha = __expf(m[i] - mnew);
            float psum = 0.0f;
            int r = ty * 4 + i;
#pragma unroll
            for (int j = 0; j < 4; j++) {
                float p = __expf(s[i][j] - mnew);
                Ps[r * PP + tx * 4 + j] = p;
                psum += p;
            }
#pragma unroll
            for (int off = 8; off >= 1; off >>= 1)
                psum += __shfl_xor_sync(0xffffffffu, psum, off);
            l[i] = l[i] * alpha + psum;
            m[i] = mnew;
#pragma unroll
            for (int j = 0; j < 6; j++) acc[i][j] *= alpha;
        }
        __syncthreads();

#pragma unroll 4
        for (int kk = 0; kk < BKV; kk++) {
            float vv[6];
#pragma unroll
            for (int j = 0; j < 6; j++) vv[j] = Vs[kk * HD + tx * 6 + j];
#pragma unroll
            for (int i = 0; i < 4; i++) {
                float p = Ps[(ty * 4 + i) * PP + kk];
#pragma unroll
                for (int j = 0; j < 6; j++)
                    acc[i][j] = fmaf(p, vv[j], acc[i][j]);
            }
        }
    }

    // write tf32-rounded (feeds the second TF32 GEMM directly)
#pragma unroll
    for (int i = 0; i < 4; i++) {
        int lrow = qt * BQ + ty * 4 + i;
        float inv = 1.0f / l[i];
        float* op = out + (size_t)(b * LL + lrow) * HIDDEN + h * HD + tx * 6;
#pragma unroll
        for (int j = 0; j < 6; j++) op[j] = tf32r(acc[i][j] * inv);
    }
}

// ---------------- launch ----------------
extern "C" void kernel_launch(void* const* d_in, const int* in_sizes, int n_in,
                              void* d_out, int out_size)
{
    const float* x    = (const float*)d_in[0];
    const float* Wqkv = (const float*)d_in[1];
    const float* Wo   = (const float*)d_in[2];
    float* out = (float*)d_out;

    float* qkv;  cudaGetSymbolAddress((void**)&qkv,  g_qkv);
    float* attn; cudaGetSymbolAddress((void**)&attn, g_attn);
    float* xr;   cudaGetSymbolAddress((void**)&xr,   g_x);
    float* wq;   cudaGetSymbolAddress((void**)&wq,   g_wq);
    float* wo;   cudaGetSymbolAddress((void**)&wo,   g_wo);

    static const int flash_smem = FLASH_SMEM_FLOATS * (int)sizeof(float);
    cudaFuncSetAttribute(flash_kernel,
                         cudaFuncAttributeMaxDynamicSharedMemorySize, flash_smem);
    cudaFuncSetAttribute(gemm_tf32_nt_kernel,
                         cudaFuncAttributeMaxDynamicSharedMemorySize, GEMM_SMEM_BYTES);

    // 0) tf32 pre-round of GEMM inputs
    {
        int n4x = MTOK * HIDDEN / 4;
        round_tf32_kernel<<<(n4x + 255) / 256, 256>>>(x, xr, n4x);
        int n4q = OPSZ * HIDDEN / 4;
        round_tf32_kernel<<<(n4q + 255) / 256, 256>>>(Wqkv, wq, n4q);
        int n4o = HIDDEN * HIDDEN / 4;
        round_tf32_kernel<<<(n4o + 255) / 256, 256>>>(Wo, wo, n4o);
    }
    // 1) QKV = x @ Wqkv^T : [4096, 9216]
    {
        dim3 grid(OPSZ / 256, MTOK / 128);
        gemm_tf32_nt_kernel<<<grid, 256, GEMM_SMEM_BYTES>>>(xr, wq, qkv, MTOK, OPSZ, HIDDEN);
    }
    // 2) RoPE
    {
        int n1 = LL * 48;
        rope_table_kernel<<<(n1 + 255) / 256, 256>>>();
        int n2 = MTOK * NH * 48;
        rope_apply_kernel<<<(n2 + 255) / 256, 256>>>();
    }
    // 3) flash attention -> attn [4096, 3072] (tf32-rounded)
    {
        dim3 grid(LL / BQ, BB * NH);
        flash_kernel<<<grid, 256, flash_smem>>>(qkv, attn);
    }
    // 4) out = attn @ Wo^T : [4096, 3072]
    {
        dim3 grid(HIDDEN / 256, MTOK / 128);
        gemm_tf32_nt_kernel<<<grid, 256, GEMM_SMEM_BYTES>>>(attn, wo, out, MTOK, HIDDEN, HIDDEN);
    }
}